// round 1
// baseline (speedup 1.0000x reference)
#include <cuda_runtime.h>

// ============================================================================
// GCN: 3-layer, N~100k nodes, E~1.6M edges, D=H=128, C=64, fp32.
//   per layer: h = X @ W ; out[dst] = sum_{(src,dst)} dinv[src]*dinv[dst]*h[src]
//              + dinv[dst]^2 * h[dst] (self loop) + b ; relu after layer 0.
// Strategy:
//   - Build CSR (by dst) + dinv once per launch; reuse for 3 layers.
//   - Pull-mode aggregation: one warp per node, no atomics in hot loop,
//     float4/float2 row gathers (L2-resident: 2x51MB buffers < 126MB L2).
//   - SIMT fp32 GEMM with W + X-tile staged in smem, packed fma.rn.f32x2
//     (2 FMAs/instr on Blackwell) -> ~2x scalar FFMA throughput.
//   - edge_index dtype (int32 vs int64) sniffed on device.
// ============================================================================

#define MAX_N 131072
#define MAX_E 2097152

__device__ float g_bufA[(size_t)MAX_N * 128];
__device__ float g_bufB[(size_t)MAX_N * 128];
__device__ float g_dinv[MAX_N];
__device__ int   g_rowptr[MAX_N + 1];
__device__ int   g_cursor[MAX_N + 1];
__device__ int   g_col[MAX_E];
__device__ int   g_is64;

// ---------------------------------------------------------------------------
// dtype sniffer: int64 indices < 2^17 => every odd 32-bit word is 0.
// ---------------------------------------------------------------------------
__global__ void detect_kernel(const unsigned* __restrict__ words, int nwords) {
    __shared__ int any;
    if (threadIdx.x == 0) any = 0;
    __syncthreads();
    int found = 0;
    for (int i = threadIdx.x; 2 * i + 1 < nwords; i += blockDim.x) {
        if (words[2 * i + 1] != 0u) { found = 1; break; }
    }
    if (found) atomicOr(&any, 1);
    __syncthreads();
    if (threadIdx.x == 0) g_is64 = any ? 0 : 1;
}

__global__ void zero_kernel(int n) {
    int i = blockIdx.x * blockDim.x + threadIdx.x;
    if (i < n) g_cursor[i] = 0;
}

__global__ void count_kernel(const void* __restrict__ edges, int E) {
    int e = blockIdx.x * blockDim.x + threadIdx.x;
    if (e >= E) return;
    int dst;
    if (g_is64) dst = (int)((const long long*)edges)[E + e];
    else        dst = ((const int*)edges)[E + e];
    atomicAdd(&g_cursor[dst], 1);
}

// Single-block scan: rowptr (exclusive), cursor copy, dinv = rsqrt(deg+1).
__global__ void scan_kernel(int N, int E) {
    __shared__ int sh[1024];
    int t = threadIdx.x;
    int chunk = (N + 1023) / 1024;
    int lo = t * chunk;
    int hi = lo + chunk; if (hi > N) hi = N; if (lo > N) lo = N;
    int s = 0;
    for (int i = lo; i < hi; i++) s += g_cursor[i];
    sh[t] = s;
    __syncthreads();
    for (int off = 1; off < 1024; off <<= 1) {
        int v = (t >= off) ? sh[t - off] : 0;
        __syncthreads();
        sh[t] += v;
        __syncthreads();
    }
    int run = sh[t] - s;  // exclusive prefix
    for (int i = lo; i < hi; i++) {
        int d = g_cursor[i];
        g_rowptr[i] = run;
        g_cursor[i] = run;
        g_dinv[i] = rsqrtf((float)(d + 1));  // +1 self loop
        run += d;
    }
    if (t == 1023) g_rowptr[N] = sh[1023];
    (void)E;
}

__global__ void fill_kernel(const void* __restrict__ edges, int E) {
    int e = blockIdx.x * blockDim.x + threadIdx.x;
    if (e >= E) return;
    int src, dst;
    if (g_is64) {
        src = (int)((const long long*)edges)[e];
        dst = (int)((const long long*)edges)[E + e];
    } else {
        src = ((const int*)edges)[e];
        dst = ((const int*)edges)[E + e];
    }
    int pos = atomicAdd(&g_cursor[dst], 1);
    g_col[pos] = src;
}

// ---------------------------------------------------------------------------
// GEMM: Y[N,K] = X[N,D] @ W[D,K], D=128, K in {128,64}.
// 256 threads, 64 rows/block. W + padded X-tile in smem.
// Packed fma.rn.f32x2: 2 fp32 FMAs per instruction.
// ---------------------------------------------------------------------------
template <int D, int K>
__global__ void __launch_bounds__(256) gemm_kernel(
    const float* __restrict__ X, const float* __restrict__ W,
    float* __restrict__ Y, int N)
{
    extern __shared__ float sm[];
    float* ws = sm;                 // D*K
    float* xs = sm + D * K;         // 64*(D+1), padded => conflict-free
    const int TR = 64;
    int tid = threadIdx.x;
    int row0 = blockIdx.x * TR;

    for (int i = tid; i < D * K; i += 256) ws[i] = W[i];
    for (int i = tid; i < TR * D; i += 256) {
        int r = i / D, k = i - r * D;
        int gr = row0 + r;
        xs[r * (D + 1) + k] = (gr < N) ? X[(size_t)gr * D + k] : 0.f;
    }
    __syncthreads();

    const int cg = tid >> 6;        // 0..3 (uniform per warp)
    const int r  = tid & 63;
    constexpr int KC = K / 4;       // cols per thread: 32 or 16
    constexpr int NA = KC / 2;      // packed accumulators
    unsigned long long acc2[NA];
    #pragma unroll
    for (int j = 0; j < NA; j++) acc2[j] = 0ull;

    const unsigned long long* ws64 = (const unsigned long long*)ws;
    const int cbase = cg * KC;

    for (int k = 0; k < D; k++) {
        float xv = xs[r * (D + 1) + k];
        unsigned long long xv2;
        asm("mov.b64 %0, {%1, %1};" : "=l"(xv2) : "f"(xv));
        const int wb = (k * K + cbase) >> 1;
        #pragma unroll
        for (int j = 0; j < NA; j++) {
            asm("fma.rn.f32x2 %0, %1, %2, %0;"
                : "+l"(acc2[j]) : "l"(xv2), "l"(ws64[wb + j]));
        }
    }

    int gr = row0 + r;
    if (gr < N) {
        float* yr = Y + (size_t)gr * K + cbase;
        #pragma unroll
        for (int j = 0; j < NA; j++) {
            float lo, hi;
            asm("mov.b64 {%0, %1}, %2;" : "=f"(lo), "=f"(hi) : "l"(acc2[j]));
            float2 v; v.x = lo; v.y = hi;
            *(float2*)(yr + 2 * j) = v;
        }
    }
}

// ---------------------------------------------------------------------------
// Aggregation: one warp per node, pull over CSR in-edges, + self loop + bias.
// ---------------------------------------------------------------------------
__device__ __forceinline__ void loadv(const float* p, float (&v)[4]) {
    float4 t = *(const float4*)p; v[0] = t.x; v[1] = t.y; v[2] = t.z; v[3] = t.w;
}
__device__ __forceinline__ void loadv(const float* p, float (&v)[2]) {
    float2 t = *(const float2*)p; v[0] = t.x; v[1] = t.y;
}
__device__ __forceinline__ void storev(float* p, const float (&v)[4]) {
    float4 t; t.x = v[0]; t.y = v[1]; t.z = v[2]; t.w = v[3];
    *(float4*)p = t;
}
__device__ __forceinline__ void storev(float* p, const float (&v)[2]) {
    float2 t; t.x = v[0]; t.y = v[1];
    *(float2*)p = t;
}

template <int K, bool RELU>
__global__ void __launch_bounds__(256) aggregate_kernel(
    const float* __restrict__ H, const float* __restrict__ bias,
    float* __restrict__ out, int N)
{
    constexpr int VEC = K / 32;     // 4 (K=128) or 2 (K=64)
    int gw   = (int)((blockIdx.x * blockDim.x + threadIdx.x) >> 5);
    int lane = threadIdx.x & 31;
    if (gw >= N) return;

    const float di = g_dinv[gw];
    const int col0 = lane * VEC;

    float acc[VEC];
    {   // self loop: dinv[i]^2 * h[i]
        float v[VEC];
        loadv(H + (size_t)gw * K + col0, v);
        const float w = di * di;
        #pragma unroll
        for (int c = 0; c < VEC; c++) acc[c] = w * v[c];
    }

    int j = g_rowptr[gw];
    const int jend = g_rowptr[gw + 1];
    for (; j + 2 <= jend; j += 2) {
        int s0 = g_col[j], s1 = g_col[j + 1];
        float w0 = di * g_dinv[s0];
        float w1 = di * g_dinv[s1];
        float v0[VEC], v1[VEC];
        loadv(H + (size_t)s0 * K + col0, v0);
        loadv(H + (size_t)s1 * K + col0, v1);
        #pragma unroll
        for (int c = 0; c < VEC; c++) acc[c] = fmaf(w0, v0[c], acc[c]);
        #pragma unroll
        for (int c = 0; c < VEC; c++) acc[c] = fmaf(w1, v1[c], acc[c]);
    }
    if (j < jend) {
        int s0 = g_col[j];
        float w0 = di * g_dinv[s0];
        float v0[VEC];
        loadv(H + (size_t)s0 * K + col0, v0);
        #pragma unroll
        for (int c = 0; c < VEC; c++) acc[c] = fmaf(w0, v0[c], acc[c]);
    }

    float bv[VEC];
    loadv(bias + col0, bv);
    #pragma unroll
    for (int c = 0; c < VEC; c++) {
        acc[c] += bv[c];
        if (RELU) acc[c] = fmaxf(acc[c], 0.f);
    }
    storev(out + (size_t)gw * K + col0, acc);
}

// ---------------------------------------------------------------------------
// Launch. Inputs (metadata order): x, edge_index, W0, b0, W1, b1, W2, b2.
// ---------------------------------------------------------------------------
extern "C" void kernel_launch(void* const* d_in, const int* in_sizes, int n_in,
                              void* d_out, int out_size) {
    const float* x     = (const float*)d_in[0];
    const void*  edges = d_in[1];
    const float* W0 = (const float*)d_in[2];
    const float* b0 = (const float*)d_in[3];
    const float* W1 = (const float*)d_in[4];
    const float* b1 = (const float*)d_in[5];
    const float* W2 = (const float*)d_in[6];
    const float* b2 = (const float*)d_in[7];
    float* out = (float*)d_out;

    const int H = in_sizes[3];            // 128
    const int C = in_sizes[7];            // 64
    const int D = in_sizes[2] / H;        // 128
    const int N = in_sizes[0] / D;        // 100000
    const int E = in_sizes[1] / 2;        // 1600000
    (void)n_in; (void)out_size;

    void *pA, *pB;
    cudaGetSymbolAddress(&pA, g_bufA);
    cudaGetSymbolAddress(&pB, g_bufB);
    float* bufA = (float*)pA;
    float* bufB = (float*)pB;

    const int smemHH = (D * H + 64 * (D + 1)) * (int)sizeof(float);  // ~98.5KB
    const int smemHC = (D * C + 64 * (D + 1)) * (int)sizeof(float);  // ~65.8KB
    cudaFuncSetAttribute(gemm_kernel<128, 128>,
                         cudaFuncAttributeMaxDynamicSharedMemorySize, smemHH);
    cudaFuncSetAttribute(gemm_kernel<128, 64>,
                         cudaFuncAttributeMaxDynamicSharedMemorySize, smemHC);

    // ---- CSR + dinv build (once, reused by all 3 layers) ----
    int nwords = 2 * E < 4096 ? 2 * E : 4096;
    detect_kernel<<<1, 256>>>((const unsigned*)edges, nwords);
    zero_kernel<<<(N + 256) / 256, 256>>>(N + 1);
    count_kernel<<<(E + 255) / 256, 256>>>(edges, E);
    scan_kernel<<<1, 1024>>>(N, E);
    fill_kernel<<<(E + 255) / 256, 256>>>(edges, E);

    const int gemmBlocks = (N + 63) / 64;
    const int aggBlocks  = (N + 7) / 8;   // 8 warps/block, 1 warp/node

    // ---- layer 0: x@W0 -> aggregate + b0 + relu ----
    gemm_kernel<128, 128><<<gemmBlocks, 256, smemHH>>>(x, W0, bufA, N);
    aggregate_kernel<128, true><<<aggBlocks, 256>>>(bufA, b0, bufB, N);

    // ---- layer 1: h@W1 -> aggregate + b1 ----
    gemm_kernel<128, 128><<<gemmBlocks, 256, smemHH>>>(bufB, W1, bufA, N);
    aggregate_kernel<128, false><<<aggBlocks, 256>>>(bufA, b1, bufB, N);

    // ---- layer 2: h@W2 -> aggregate + b2 -> d_out ----
    gemm_kernel<128, 64><<<gemmBlocks, 256, smemHC>>>(bufB, W2, bufA, N);
    aggregate_kernel<64, false><<<aggBlocks, 256>>>(bufA, b2, out, N);
}

// round 2
// speedup vs baseline: 1.3107x; 1.3107x over previous
#include <cuda_runtime.h>

// ============================================================================
// GCN: 3-layer, N~100k nodes, E~1.6M edges, D=H=128, C=64, fp32.
// R1 change: replace single-block scan_kernel (209.7us measured, 1 SM used)
// with 3-phase chip-wide scan (scanA/scanB/scanC). Everything else unchanged.
// ============================================================================

#define MAX_N 131072
#define MAX_E 2097152
#define NB_MAX 256

__device__ float g_bufA[(size_t)MAX_N * 128];
__device__ float g_bufB[(size_t)MAX_N * 128];
__device__ float g_dinv[MAX_N];
__device__ int   g_rowptr[MAX_N + 1];
__device__ int   g_cursor[MAX_N + 1];
__device__ int   g_col[MAX_E];
__device__ int   g_blkSum[NB_MAX];
__device__ int   g_is64;

// ---------------------------------------------------------------------------
// dtype sniffer: int64 indices < 2^17 => every odd 32-bit word is 0.
// ---------------------------------------------------------------------------
__global__ void detect_kernel(const unsigned* __restrict__ words, int nwords) {
    __shared__ int any;
    if (threadIdx.x == 0) any = 0;
    __syncthreads();
    int found = 0;
    for (int i = threadIdx.x; 2 * i + 1 < nwords; i += blockDim.x) {
        if (words[2 * i + 1] != 0u) { found = 1; break; }
    }
    if (found) atomicOr(&any, 1);
    __syncthreads();
    if (threadIdx.x == 0) g_is64 = any ? 0 : 1;
}

__global__ void zero_kernel(int n) {
    int i = blockIdx.x * blockDim.x + threadIdx.x;
    if (i < n) g_cursor[i] = 0;
}

__global__ void count_kernel(const void* __restrict__ edges, int E) {
    int e = blockIdx.x * blockDim.x + threadIdx.x;
    if (e >= E) return;
    int dst;
    if (g_is64) dst = (int)((const long long*)edges)[E + e];
    else        dst = ((const int*)edges)[E + e];
    atomicAdd(&g_cursor[dst], 1);
}

// ---------------------------------------------------------------------------
// 3-phase exclusive scan of g_cursor[0..N) -> rowptr/cursor, plus dinv.
// Covers N+1 slots so rowptr[N] = total falls out naturally.
// ---------------------------------------------------------------------------
__global__ void __launch_bounds__(1024) scanA_kernel(int N) {
    __shared__ int sh[1024];
    int i = blockIdx.x * 1024 + threadIdx.x;
    sh[threadIdx.x] = (i < N) ? g_cursor[i] : 0;
    __syncthreads();
    #pragma unroll
    for (int off = 512; off > 0; off >>= 1) {
        if (threadIdx.x < off) sh[threadIdx.x] += sh[threadIdx.x + off];
        __syncthreads();
    }
    if (threadIdx.x == 0) g_blkSum[blockIdx.x] = sh[0];
}

__global__ void __launch_bounds__(NB_MAX) scanB_kernel(int nb) {
    __shared__ int sh[NB_MAX];
    int t = threadIdx.x;
    int v = (t < nb) ? g_blkSum[t] : 0;
    sh[t] = v;
    __syncthreads();
    #pragma unroll
    for (int off = 1; off < NB_MAX; off <<= 1) {
        int u = (t >= off) ? sh[t - off] : 0;
        __syncthreads();
        sh[t] += u;
        __syncthreads();
    }
    if (t < nb) g_blkSum[t] = sh[t] - v;   // exclusive
}

__global__ void __launch_bounds__(1024) scanC_kernel(int N) {
    __shared__ int sh[1024];
    int t = threadIdx.x;
    int i = blockIdx.x * 1024 + t;
    int c = (i < N) ? g_cursor[i] : 0;
    sh[t] = c;
    __syncthreads();
    for (int off = 1; off < 1024; off <<= 1) {
        int u = (t >= off) ? sh[t - off] : 0;
        __syncthreads();
        sh[t] += u;
        __syncthreads();
    }
    int excl = sh[t] - c + g_blkSum[blockIdx.x];
    if (i <= N) {
        g_rowptr[i] = excl;
        if (i < N) {
            g_cursor[i] = excl;
            g_dinv[i] = rsqrtf((float)(c + 1));   // +1 self loop
        }
    }
}

__global__ void fill_kernel(const void* __restrict__ edges, int E) {
    int e = blockIdx.x * blockDim.x + threadIdx.x;
    if (e >= E) return;
    int src, dst;
    if (g_is64) {
        src = (int)((const long long*)edges)[e];
        dst = (int)((const long long*)edges)[E + e];
    } else {
        src = ((const int*)edges)[e];
        dst = ((const int*)edges)[E + e];
    }
    int pos = atomicAdd(&g_cursor[dst], 1);
    g_col[pos] = src;
}

// ---------------------------------------------------------------------------
// GEMM: Y[N,K] = X[N,D] @ W[D,K], D=128, K in {128,64}.
// 256 threads, 64 rows/block. W + padded X-tile in smem.
// Packed fma.rn.f32x2: 2 fp32 FMAs per instruction.
// ---------------------------------------------------------------------------
template <int D, int K>
__global__ void __launch_bounds__(256) gemm_kernel(
    const float* __restrict__ X, const float* __restrict__ W,
    float* __restrict__ Y, int N)
{
    extern __shared__ float sm[];
    float* ws = sm;                 // D*K
    float* xs = sm + D * K;         // 64*(D+1), padded => conflict-free
    const int TR = 64;
    int tid = threadIdx.x;
    int row0 = blockIdx.x * TR;

    for (int i = tid; i < D * K; i += 256) ws[i] = W[i];
    for (int i = tid; i < TR * D; i += 256) {
        int r = i / D, k = i - r * D;
        int gr = row0 + r;
        xs[r * (D + 1) + k] = (gr < N) ? X[(size_t)gr * D + k] : 0.f;
    }
    __syncthreads();

    const int cg = tid >> 6;        // 0..3 (uniform per warp)
    const int r  = tid & 63;
    constexpr int KC = K / 4;       // cols per thread: 32 or 16
    constexpr int NA = KC / 2;      // packed accumulators
    unsigned long long acc2[NA];
    #pragma unroll
    for (int j = 0; j < NA; j++) acc2[j] = 0ull;

    const unsigned long long* ws64 = (const unsigned long long*)ws;
    const int cbase = cg * KC;

    for (int k = 0; k < D; k++) {
        float xv = xs[r * (D + 1) + k];
        unsigned long long xv2;
        asm("mov.b64 %0, {%1, %1};" : "=l"(xv2) : "f"(xv));
        const int wb = (k * K + cbase) >> 1;
        #pragma unroll
        for (int j = 0; j < NA; j++) {
            asm("fma.rn.f32x2 %0, %1, %2, %0;"
                : "+l"(acc2[j]) : "l"(xv2), "l"(ws64[wb + j]));
        }
    }

    int gr = row0 + r;
    if (gr < N) {
        float* yr = Y + (size_t)gr * K + cbase;
        #pragma unroll
        for (int j = 0; j < NA; j++) {
            float lo, hi;
            asm("mov.b64 {%0, %1}, %2;" : "=f"(lo), "=f"(hi) : "l"(acc2[j]));
            float2 v; v.x = lo; v.y = hi;
            *(float2*)(yr + 2 * j) = v;
        }
    }
}

// ---------------------------------------------------------------------------
// Aggregation: one warp per node, pull over CSR in-edges, + self loop + bias.
// ---------------------------------------------------------------------------
__device__ __forceinline__ void loadv(const float* p, float (&v)[4]) {
    float4 t = *(const float4*)p; v[0] = t.x; v[1] = t.y; v[2] = t.z; v[3] = t.w;
}
__device__ __forceinline__ void loadv(const float* p, float (&v)[2]) {
    float2 t = *(const float2*)p; v[0] = t.x; v[1] = t.y;
}
__device__ __forceinline__ void storev(float* p, const float (&v)[4]) {
    float4 t; t.x = v[0]; t.y = v[1]; t.z = v[2]; t.w = v[3];
    *(float4*)p = t;
}
__device__ __forceinline__ void storev(float* p, const float (&v)[2]) {
    float2 t; t.x = v[0]; t.y = v[1];
    *(float2*)p = t;
}

template <int K, bool RELU>
__global__ void __launch_bounds__(256) aggregate_kernel(
    const float* __restrict__ H, const float* __restrict__ bias,
    float* __restrict__ out, int N)
{
    constexpr int VEC = K / 32;     // 4 (K=128) or 2 (K=64)
    int gw   = (int)((blockIdx.x * blockDim.x + threadIdx.x) >> 5);
    int lane = threadIdx.x & 31;
    if (gw >= N) return;

    const float di = g_dinv[gw];
    const int col0 = lane * VEC;

    float acc[VEC];
    {   // self loop: dinv[i]^2 * h[i]
        float v[VEC];
        loadv(H + (size_t)gw * K + col0, v);
        const float w = di * di;
        #pragma unroll
        for (int c = 0; c < VEC; c++) acc[c] = w * v[c];
    }

    int j = g_rowptr[gw];
    const int jend = g_rowptr[gw + 1];
    for (; j + 2 <= jend; j += 2) {
        int s0 = g_col[j], s1 = g_col[j + 1];
        float w0 = di * g_dinv[s0];
        float w1 = di * g_dinv[s1];
        float v0[VEC], v1[VEC];
        loadv(H + (size_t)s0 * K + col0, v0);
        loadv(H + (size_t)s1 * K + col0, v1);
        #pragma unroll
        for (int c = 0; c < VEC; c++) acc[c] = fmaf(w0, v0[c], acc[c]);
        #pragma unroll
        for (int c = 0; c < VEC; c++) acc[c] = fmaf(w1, v1[c], acc[c]);
    }
    if (j < jend) {
        int s0 = g_col[j];
        float w0 = di * g_dinv[s0];
        float v0[VEC];
        loadv(H + (size_t)s0 * K + col0, v0);
        #pragma unroll
        for (int c = 0; c < VEC; c++) acc[c] = fmaf(w0, v0[c], acc[c]);
    }

    float bv[VEC];
    loadv(bias + col0, bv);
    #pragma unroll
    for (int c = 0; c < VEC; c++) {
        acc[c] += bv[c];
        if (RELU) acc[c] = fmaxf(acc[c], 0.f);
    }
    storev(out + (size_t)gw * K + col0, acc);
}

// ---------------------------------------------------------------------------
// Launch. Inputs (metadata order): x, edge_index, W0, b0, W1, b1, W2, b2.
// ---------------------------------------------------------------------------
extern "C" void kernel_launch(void* const* d_in, const int* in_sizes, int n_in,
                              void* d_out, int out_size) {
    const float* x     = (const float*)d_in[0];
    const void*  edges = d_in[1];
    const float* W0 = (const float*)d_in[2];
    const float* b0 = (const float*)d_in[3];
    const float* W1 = (const float*)d_in[4];
    const float* b1 = (const float*)d_in[5];
    const float* W2 = (const float*)d_in[6];
    const float* b2 = (const float*)d_in[7];
    float* out = (float*)d_out;

    const int H = in_sizes[3];            // 128
    const int C = in_sizes[7];            // 64
    const int D = in_sizes[2] / H;        // 128
    const int N = in_sizes[0] / D;        // 100000
    const int E = in_sizes[1] / 2;        // 1600000
    (void)n_in; (void)out_size;

    void *pA, *pB;
    cudaGetSymbolAddress(&pA, g_bufA);
    cudaGetSymbolAddress(&pB, g_bufB);
    float* bufA = (float*)pA;
    float* bufB = (float*)pB;

    const int smemHH = (D * H + 64 * (D + 1)) * (int)sizeof(float);  // ~98.5KB
    const int smemHC = (D * C + 64 * (D + 1)) * (int)sizeof(float);  // ~65.8KB
    cudaFuncSetAttribute(gemm_kernel<128, 128>,
                         cudaFuncAttributeMaxDynamicSharedMemorySize, smemHH);
    cudaFuncSetAttribute(gemm_kernel<128, 64>,
                         cudaFuncAttributeMaxDynamicSharedMemorySize, smemHC);

    // ---- CSR + dinv build (once, reused by all 3 layers) ----
    int nwords = 2 * E < 4096 ? 2 * E : 4096;
    detect_kernel<<<1, 256>>>((const unsigned*)edges, nwords);
    zero_kernel<<<(N + 256) / 256, 256>>>(N + 1);
    count_kernel<<<(E + 255) / 256, 256>>>(edges, E);
    const int nb = (N + 1 + 1023) / 1024;   // covers slot i==N
    scanA_kernel<<<nb, 1024>>>(N);
    scanB_kernel<<<1, NB_MAX>>>(nb);
    scanC_kernel<<<nb, 1024>>>(N);
    fill_kernel<<<(E + 255) / 256, 256>>>(edges, E);

    const int gemmBlocks = (N + 63) / 64;
    const int aggBlocks  = (N + 7) / 8;   // 8 warps/block, 1 warp/node

    // ---- layer 0: x@W0 -> aggregate + b0 + relu ----
    gemm_kernel<128, 128><<<gemmBlocks, 256, smemHH>>>(x, W0, bufA, N);
    aggregate_kernel<128, true><<<aggBlocks, 256>>>(bufA, b0, bufB, N);

    // ---- layer 1: h@W1 -> aggregate + b1 ----
    gemm_kernel<128, 128><<<gemmBlocks, 256, smemHH>>>(bufB, W1, bufA, N);
    aggregate_kernel<128, false><<<aggBlocks, 256>>>(bufA, b1, bufB, N);

    // ---- layer 2: h@W2 -> aggregate + b2 -> d_out ----
    gemm_kernel<128, 64><<<gemmBlocks, 256, smemHC>>>(bufB, W2, bufA, N);
    aggregate_kernel<64, false><<<aggBlocks, 256>>>(bufA, b2, out, N);
}